// round 15
// baseline (speedup 1.0000x reference)
#include <cuda_runtime.h>
#include <cuda_bf16.h>

// Problem constants
#define B_    16
#define CIN_  64
#define COUT_ 64
#define H_    130
#define W_    130
#define HO_   128
#define WO_   128
#define G_    8
#define CPG_  8
#define SP_   (HO_*WO_)      // 16384
#define OFFC_ (G_*2*9)       // 144
#define YSIZE_ ((size_t)B_*COUT_*SP_)   // 16777216

typedef unsigned long long u64;

// Packed f32x2 helpers (FFMA2 — ptxas never emits this from C++)
__device__ __forceinline__ u64 pack2(float a, float b) {
    u64 r;
    asm("mov.b64 %0, {%1, %2};" : "=l"(r)
        : "r"(__float_as_uint(a)), "r"(__float_as_uint(b)));
    return r;
}
__device__ __forceinline__ void fma2(u64& d, u64 a, u64 b) {
    asm("fma.rn.f32x2 %0, %1, %2, %0;" : "+l"(d) : "l"(a), "l"(b));
}
__device__ __forceinline__ float lo32(u64 v) { return __uint_as_float((unsigned)v); }
__device__ __forceinline__ float hi32(u64 v) { return __uint_as_float((unsigned)(v >> 32)); }

// cp.async (LDGSTS) helpers — bypass L1 for bulk smem fills
__device__ __forceinline__ void cp16(float* s, const float* g) {
    unsigned sa = (unsigned)__cvta_generic_to_shared(s);
    asm volatile("cp.async.cg.shared.global [%0], [%1], 16;\n" :: "r"(sa), "l"(g));
}
#define CP_COMMIT() asm volatile("cp.async.commit_group;\n" ::: "memory")
#define CP_WAIT0()  asm volatile("cp.async.wait_group 0;\n" ::: "memory")

// Scratch (no allocation allowed -> device globals)
__device__ __align__(16) float g_t1[(size_t)B_*CIN_*SP_];    // conv1 output
__device__ __align__(16) float g_w1t[CIN_*9*CIN_];           // [ci][tap][co]
__device__ __align__(16) float g_w2t[CIN_*OFFC_];            // [ci][oc]
__device__ __align__(16) float g_wdup[576*128];              // [k][2*co dup pairs]

// ---------------------------------------------------------------------------
// Prep: transpose weights once so all later smem fills are coalesced.
// g_wdup[k][2c] = g_wdup[k][2c+1] = wd[c][k] — ready-made f32x2 broadcast pairs.
// ---------------------------------------------------------------------------
__global__ void prep_kernel(const float* __restrict__ w1,
                            const float* __restrict__ w2,
                            const float* __restrict__ wd) {
    int idx = blockIdx.x * 256 + threadIdx.x;
    if (idx < 36864) {                       // w1t[ci][tap][co]
        int co = idx & 63;
        int rest = idx >> 6;
        int tap = rest % 9;
        int ci  = rest / 9;
        g_w1t[idx] = w1[co*576 + ci*9 + tap];
    }
    int j2 = idx - 36864;
    if (j2 >= 0 && j2 < 9216) {              // w2t[ci][oc]
        int oc = j2 % 144;
        int ci = j2 / 144;
        g_w2t[j2] = w2[oc*64 + ci];
    }
    int j4 = idx - 46080;
    if (j4 >= 0 && j4 < 73728) {             // wdup[k][col], col=2c or 2c+1
        int col = j4 & 127;
        int k   = j4 >> 7;
        int c   = col >> 1;
        g_wdup[j4] = wd[c*576 + k];
    }
}

// ---------------------------------------------------------------------------
// conv1: 3x3 VALID, 64->64.  Block: 32x16 pixel tile x 16 couts.
// Each thread: 2 pixels x 16 couts, f32x2 accumulators. cin chunks of 8.
// (FFMA2-bound — unchanged.)
// ---------------------------------------------------------------------------
__global__ __launch_bounds__(256) void conv1_kernel(const float* __restrict__ x,
                                                    const float* __restrict__ b1) {
    __shared__ __align__(16) float xs[8][18][34];  // 19.1KB
    __shared__ __align__(16) float ws[8][9][16];   // [ci][tap][cc] 4.6KB

    int tid = threadIdx.x;
    int tx = tid & 15, ty = tid >> 4;       // ty 0..15
    int c0 = blockIdx.x * 32;
    int r0 = blockIdx.y * 16;
    int bz = blockIdx.z;                    // b*4 + cog
    int b  = bz >> 2, cog = bz & 3;

    u64 accA[8], accB[8];
#pragma unroll
    for (int i = 0; i < 8; ++i) { accA[i] = 0ull; accB[i] = 0ull; }

    for (int ch = 0; ch < 8; ++ch) {
        int ci0 = ch * 8;
        __syncthreads();
        for (int idx = tid; idx < 8*18*34; idx += 256) {
            int ci = idx / 612;
            int rem = idx - ci*612;
            int r = rem / 34;
            int c = rem - r*34;
            xs[ci][r][c] = x[(((size_t)b*64 + ci0+ci)*130 + (r0+r))*130 + (c0+c)];
        }
        for (int idx = tid; idx < 1152; idx += 256) {
            int cc = idx & 15;
            int rest = idx >> 4;
            int tap = rest % 9;
            int ci  = rest / 9;
            ws[ci][tap][cc] = g_w1t[(ci0+ci)*576 + tap*64 + cog*16 + cc];
        }
        __syncthreads();

#pragma unroll
        for (int ci = 0; ci < 8; ++ci) {
            float xvA[9], xvB[9];
#pragma unroll
            for (int di = 0; di < 3; ++di)
#pragma unroll
                for (int dj = 0; dj < 3; ++dj) {
                    xvA[di*3+dj] = xs[ci][ty+di][tx+dj];
                    xvB[di*3+dj] = xs[ci][ty+di][tx+16+dj];
                }
#pragma unroll
            for (int tap = 0; tap < 9; ++tap) {
                const ulonglong2* wp = (const ulonglong2*)&ws[ci][tap][0];
                ulonglong2 w01 = wp[0], w23 = wp[1], w45 = wp[2], w67 = wp[3];
                u64 vA = pack2(xvA[tap], xvA[tap]);
                u64 vB = pack2(xvB[tap], xvB[tap]);
                fma2(accA[0], vA, w01.x); fma2(accA[1], vA, w01.y);
                fma2(accA[2], vA, w23.x); fma2(accA[3], vA, w23.y);
                fma2(accA[4], vA, w45.x); fma2(accA[5], vA, w45.y);
                fma2(accA[6], vA, w67.x); fma2(accA[7], vA, w67.y);
                fma2(accB[0], vB, w01.x); fma2(accB[1], vB, w01.y);
                fma2(accB[2], vB, w23.x); fma2(accB[3], vB, w23.y);
                fma2(accB[4], vB, w45.x); fma2(accB[5], vB, w45.y);
                fma2(accB[6], vB, w67.x); fma2(accB[7], vB, w67.y);
            }
        }
    }
    size_t obase = ((size_t)b*64 + cog*16) << 14;
    int pA = (r0+ty)*128 + (c0+tx);
    int pB = pA + 16;
#pragma unroll
    for (int p = 0; p < 8; ++p) {
        float bl = __ldg(&b1[cog*16 + 2*p]);
        float bh = __ldg(&b1[cog*16 + 2*p + 1]);
        g_t1[obase + ((size_t)(2*p)   << 14) + pA] = lo32(accA[p]) + bl;
        g_t1[obase + ((size_t)(2*p+1) << 14) + pA] = hi32(accA[p]) + bh;
        g_t1[obase + ((size_t)(2*p)   << 14) + pB] = lo32(accB[p]) + bl;
        g_t1[obase + ((size_t)(2*p+1) << 14) + pB] = hi32(accB[p]) + bh;
    }
}

// ---------------------------------------------------------------------------
// conv2: 1x1, 64->144 (offsets). Block: 64 pixels x 144 oc.
// cp.async fills, double-buffered t1 tile.
// ---------------------------------------------------------------------------
__global__ __launch_bounds__(256) void conv2_kernel(const float* __restrict__ b2,
                                                    float* __restrict__ out_off) {
    __shared__ __align__(16) float w2s[64*144];    // [ci][oc]  36.9KB
    __shared__ __align__(16) float ts[2][16*64];   // [buf][ci*64+pix]  8KB

    int tid = threadIdx.x;
    int pix = tid & 63, ocg = tid >> 6;            // ocg 0..3
    int p0 = blockIdx.x * 64;
    int b  = p0 >> 14;
    int sp = p0 & 16383;

    const float* t1b = g_t1 + (size_t)b*64*16384 + sp;

    for (int i = tid; i < 2304; i += 256) cp16(&w2s[i*4], &g_w2t[i*4]);
    {
        int ci = tid >> 4, q = (tid & 15) * 4;
        cp16(&ts[0][ci*64 + q], t1b + (size_t)ci*16384 + q);
    }
    CP_COMMIT();

    u64 acc[18];
#pragma unroll
    for (int i = 0; i < 18; ++i) acc[i] = 0ull;

    for (int ch = 0; ch < 4; ++ch) {
        CP_WAIT0();
        __syncthreads();
        if (ch < 3) {
            int ci = tid >> 4, q = (tid & 15) * 4;
            cp16(&ts[(ch+1) & 1][ci*64 + q],
                 t1b + (size_t)((ch+1)*16 + ci)*16384 + q);
            CP_COMMIT();
        }
        const float* tsc = ts[ch & 1];
#pragma unroll
        for (int ci = 0; ci < 16; ++ci) {
            float xv = tsc[ci*64 + pix];
            u64 xv2 = pack2(xv, xv);
            const ulonglong2* wp = (const ulonglong2*)&w2s[(ch*16 + ci)*144];
#pragma unroll
            for (int m = 0; m < 9; ++m) {
                ulonglong2 w = wp[ocg + m*4];      // oc = ocg*4 + m*16 + {0..3}
                fma2(acc[2*m],   xv2, w.x);
                fma2(acc[2*m+1], xv2, w.y);
            }
        }
        if (ch < 3) __syncthreads();
    }
    float* ob = out_off + (size_t)b*144*16384 + sp + pix;
#pragma unroll
    for (int m = 0; m < 9; ++m) {
        int oc = ocg*4 + m*16;
        ob[(size_t)(oc  )*16384] = lo32(acc[2*m])   + __ldg(&b2[oc]);
        ob[(size_t)(oc+1)*16384] = hi32(acc[2*m])   + __ldg(&b2[oc+1]);
        ob[(size_t)(oc+2)*16384] = lo32(acc[2*m+1]) + __ldg(&b2[oc+2]);
        ob[(size_t)(oc+3)*16384] = hi32(acc[2*m+1]) + __ldg(&b2[oc+3]);
    }
}

// ---------------------------------------------------------------------------
// deform conv: phase 1 builds interpolated 576-vector per pixel into smem;
// phase 2 is a smem GEMM [64x576]x[576x32] with pixel-paired f32x2 accs and
// pre-duplicated weights (zero MOV-packing in the inner loop).
// Block: 32 pixels of one row. Smem: 576*32*4 + 2*32*128*4 = 106496 B.
// ---------------------------------------------------------------------------
__global__ __launch_bounds__(256) void deform_kernel(const float* __restrict__ x,
                                                     const float* __restrict__ off,
                                                     float* __restrict__ yout) {
    extern __shared__ __align__(16) float sm[];
    float* v_s  = sm;                 // [k=0..575][pix=0..31]   73.7KB
    float* wd_s = sm + 576*32;        // 2 x [kk=0..31][128 dup] 32KB

    int tid = threadIdx.x;
    int b   = blockIdx.z;
    int ho  = blockIdx.y;
    int wo0 = blockIdx.x * 32;

    // Prefetch weight chunk 0 while phase 1 runs (32 kk x 128 = 4096 floats)
    for (int i = tid; i < 1024; i += 256) cp16(wd_s + i*4, g_wdup + i*4);
    CP_COMMIT();

    // ---- Phase 1: gather + bilinear. 72 (g,tap) x 32 pix = 2304 tasks.
#pragma unroll
    for (int t = 0; t < 9; ++t) {
        int taskid = t*256 + tid;
        int pix = taskid & 31;            // full warp = 32 pixels of one gt
        int gt  = taskid >> 5;
        int g   = gt / 9;
        int tap = gt - g*9;
        int i   = tap / 3;
        int j   = tap - i*3;
        int wo  = wo0 + pix;

        size_t ob = ((size_t)(b*144 + (g*9 + tap)*2))*16384 + (size_t)ho*128 + wo;
        float dy = off[ob];
        float dx = off[ob + 16384];
        float py = dy + (float)(ho + i);
        float px = dx + (float)(wo + j);
        float y0f = floorf(py), x0f = floorf(px);
        float ly = py - y0f, lx = px - x0f;
        int y0 = (int)y0f, x0 = (int)x0f;
        int y1 = y0 + 1,  x1 = x0 + 1;

        float my0 = (y0 >= 0 && y0 < 130) ? 1.f : 0.f;
        float my1 = (y1 >= 0 && y1 < 130) ? 1.f : 0.f;
        float mx0 = (x0 >= 0 && x0 < 130) ? 1.f : 0.f;
        float mx1 = (x1 >= 0 && x1 < 130) ? 1.f : 0.f;

        int yc0 = min(max(y0, 0), 129), yc1 = min(max(y1, 0), 129);
        int xc0 = min(max(x0, 0), 129), xc1 = min(max(x1, 0), 129);

        float a00 = (1.f-ly)*(1.f-lx)*my0*mx0;
        float a01 = (1.f-ly)*lx      *my0*mx1;
        float a10 = ly      *(1.f-lx)*my1*mx0;
        float a11 = ly      *lx      *my1*mx1;

        int i00 = yc0*130 + xc0, i01 = yc0*130 + xc1;
        int i10 = yc1*130 + xc0, i11 = yc1*130 + xc1;

        const float* xb = x + ((size_t)b*64 + g*8)*16900;
        int kbase = (g*8)*9 + tap;
#pragma unroll
        for (int c = 0; c < 8; ++c) {
            const float* xc = xb + c*16900;
            float v = a00*xc[i00] + a01*xc[i01] + a10*xc[i10] + a11*xc[i11];
            v_s[(kbase + c*9)*32 + pix] = v;
        }
    }

    // ---- Phase 2: y[co][pix] = sum_k v_s[k][pix] * wd[k][co]
    // Thread tile: 4 pixels x 2 couts. pg = pixel group (4 px), cg = cout pair.
    // Per kk: 1 LDS.128 (4 xv, 2 pix-pairs) + 1 LDS.128 (2 dup-weight pairs)
    //         + 4 FFMA2 — no packing instructions.
    int pg = tid & 7;                     // pixels 4pg .. 4pg+3
    int cg = tid >> 3;                    // couts 2cg, 2cg+1
    u64 acc00 = 0ull, acc01 = 0ull, acc10 = 0ull, acc11 = 0ull;

    for (int kc = 0; kc < 18; ++kc) {     // 18 chunks of 32 kk
        CP_WAIT0();
        __syncthreads();                  // chunk ready + prev buffer free / v_s ready
        const float* wb = wd_s + (kc & 1)*4096;
        if (kc < 17) {
            float* wn = wd_s + ((kc+1) & 1)*4096;
            const float* gsrc = g_wdup + (kc+1)*4096;
            for (int i = tid; i < 1024; i += 256) cp16(wn + i*4, gsrc + i*4);
            CP_COMMIT();
        }
        const float* vbase = v_s + kc*32*32 + pg*4;
        const float* wbase = wb + cg*4;
#pragma unroll
        for (int kk = 0; kk < 32; ++kk) {
            ulonglong2 xv = *(const ulonglong2*)(vbase + kk*32);   // (p0,p1),(p2,p3)
            ulonglong2 wd = *(const ulonglong2*)(wbase + kk*128);  // (w0,w0),(w1,w1)
            fma2(acc00, xv.x, wd.x);
            fma2(acc01, xv.x, wd.y);
            fma2(acc10, xv.y, wd.x);
            fma2(acc11, xv.y, wd.y);
        }
    }

    // Contiguous float4 store per cout row.
    float* yb = yout + ((size_t)b*64 + 2*cg)*16384 + (size_t)ho*128 + wo0 + pg*4;
    *(float4*)yb            = make_float4(lo32(acc00), hi32(acc00), lo32(acc10), hi32(acc10));
    *(float4*)(yb + 16384)  = make_float4(lo32(acc01), hi32(acc01), lo32(acc11), hi32(acc11));
}

// ---------------------------------------------------------------------------
extern "C" void kernel_launch(void* const* d_in, const int* in_sizes, int n_in,
                              void* d_out, int out_size) {
    const float* x  = (const float*)d_in[0];
    const float* w1 = (const float*)d_in[1];
    const float* b1 = (const float*)d_in[2];
    const float* w2 = (const float*)d_in[3];
    const float* b2 = (const float*)d_in[4];
    const float* wd = (const float*)d_in[5];

    float* out    = (float*)d_out;
    float* yout   = out;              // y:  [16,64,128,128]
    float* offout = out + YSIZE_;     // off:[16,144,128,128]

    const int DEFORM_SMEM = (576*32 + 2*32*128) * 4;   // 106496 B
    cudaFuncSetAttribute(deform_kernel,
                         cudaFuncAttributeMaxDynamicSharedMemorySize, DEFORM_SMEM);

    prep_kernel<<<468, 256>>>(w1, w2, wd);
    conv1_kernel<<<dim3(4, 8, 64), 256>>>(x, b1);
    conv2_kernel<<<4096, 256>>>(b2, offout);
    deform_kernel<<<dim3(4, 128, 16), 256, DEFORM_SMEM>>>(x, offout, yout);
}

// round 16
// speedup vs baseline: 1.1603x; 1.1603x over previous
#include <cuda_runtime.h>
#include <cuda_bf16.h>

// Problem constants
#define B_    16
#define CIN_  64
#define COUT_ 64
#define H_    130
#define W_    130
#define HO_   128
#define WO_   128
#define G_    8
#define CPG_  8
#define SP_   (HO_*WO_)      // 16384
#define OFFC_ (G_*2*9)       // 144
#define YSIZE_ ((size_t)B_*COUT_*SP_)   // 16777216

typedef unsigned long long u64;

// Packed f32x2 helpers (FFMA2 — ptxas never emits this from C++)
__device__ __forceinline__ u64 pack2(float a, float b) {
    u64 r;
    asm("mov.b64 %0, {%1, %2};" : "=l"(r)
        : "r"(__float_as_uint(a)), "r"(__float_as_uint(b)));
    return r;
}
__device__ __forceinline__ void fma2(u64& d, u64 a, u64 b) {
    asm("fma.rn.f32x2 %0, %1, %2, %0;" : "+l"(d) : "l"(a), "l"(b));
}
__device__ __forceinline__ float lo32(u64 v) { return __uint_as_float((unsigned)v); }
__device__ __forceinline__ float hi32(u64 v) { return __uint_as_float((unsigned)(v >> 32)); }

// cp.async (LDGSTS) helpers
__device__ __forceinline__ void cp16(float* s, const float* g) {
    unsigned sa = (unsigned)__cvta_generic_to_shared(s);
    asm volatile("cp.async.cg.shared.global [%0], [%1], 16;\n" :: "r"(sa), "l"(g));
}
#define CP_COMMIT() asm volatile("cp.async.commit_group;\n" ::: "memory")
#define CP_WAIT0()  asm volatile("cp.async.wait_group 0;\n" ::: "memory")

// Scratch (no allocation allowed -> device globals)
__device__ __align__(16) float g_t1[(size_t)B_*CIN_*SP_];    // conv1 output
__device__ __align__(16) float g_w1t[CIN_*9*CIN_];           // [ci][tap][co]
__device__ __align__(16) float g_w2t[CIN_*OFFC_];            // [ci][oc]
__device__ __align__(16) float g_wd2[576*64];                // [k'=g*72+tap*8+c][co]

// ---------------------------------------------------------------------------
// Prep: transpose weights. g_wd2 uses the (g,tap,c) k-ordering so one
// offset-group g maps to one contiguous 72-k chunk.
// ---------------------------------------------------------------------------
__global__ void prep_kernel(const float* __restrict__ w1,
                            const float* __restrict__ w2,
                            const float* __restrict__ wd) {
    int idx = blockIdx.x * 256 + threadIdx.x;
    if (idx < 36864) {                       // w1t[ci][tap][co]
        int co = idx & 63;
        int rest = idx >> 6;
        int tap = rest % 9;
        int ci  = rest / 9;
        g_w1t[idx] = w1[co*576 + ci*9 + tap];
    }
    int j2 = idx - 36864;
    if (j2 >= 0 && j2 < 9216) {              // w2t[ci][oc]
        int oc = j2 % 144;
        int ci = j2 / 144;
        g_w2t[j2] = w2[oc*64 + ci];
    }
    int j3 = idx - 46080;
    if (j3 >= 0 && j3 < 36864) {             // wd2[k'][co]
        int co = j3 & 63;
        int kp = j3 >> 6;                    // k' = g*72 + tap*8 + c
        int g   = kp / 72;
        int r   = kp - g*72;
        int tap = r >> 3;
        int c   = r & 7;
        g_wd2[j3] = wd[co*576 + (g*8 + c)*9 + tap];
    }
}

// ---------------------------------------------------------------------------
// conv1: 3x3 VALID, 64->64.  Block: 32x16 pixel tile x 16 couts.
// Each thread: 2 pixels x 16 couts, f32x2 accumulators. cin chunks of 8.
// ---------------------------------------------------------------------------
__global__ __launch_bounds__(256) void conv1_kernel(const float* __restrict__ x,
                                                    const float* __restrict__ b1) {
    __shared__ __align__(16) float xs[8][18][34];  // 19.1KB
    __shared__ __align__(16) float ws[8][9][16];   // [ci][tap][cc] 4.6KB

    int tid = threadIdx.x;
    int tx = tid & 15, ty = tid >> 4;       // ty 0..15
    int c0 = blockIdx.x * 32;
    int r0 = blockIdx.y * 16;
    int bz = blockIdx.z;                    // b*4 + cog
    int b  = bz >> 2, cog = bz & 3;

    u64 accA[8], accB[8];
#pragma unroll
    for (int i = 0; i < 8; ++i) { accA[i] = 0ull; accB[i] = 0ull; }

    for (int ch = 0; ch < 8; ++ch) {
        int ci0 = ch * 8;
        __syncthreads();
        for (int idx = tid; idx < 8*18*34; idx += 256) {
            int ci = idx / 612;
            int rem = idx - ci*612;
            int r = rem / 34;
            int c = rem - r*34;
            xs[ci][r][c] = x[(((size_t)b*64 + ci0+ci)*130 + (r0+r))*130 + (c0+c)];
        }
        for (int idx = tid; idx < 1152; idx += 256) {
            int cc = idx & 15;
            int rest = idx >> 4;
            int tap = rest % 9;
            int ci  = rest / 9;
            ws[ci][tap][cc] = g_w1t[(ci0+ci)*576 + tap*64 + cog*16 + cc];
        }
        __syncthreads();

#pragma unroll
        for (int ci = 0; ci < 8; ++ci) {
            float xvA[9], xvB[9];
#pragma unroll
            for (int di = 0; di < 3; ++di)
#pragma unroll
                for (int dj = 0; dj < 3; ++dj) {
                    xvA[di*3+dj] = xs[ci][ty+di][tx+dj];
                    xvB[di*3+dj] = xs[ci][ty+di][tx+16+dj];
                }
#pragma unroll
            for (int tap = 0; tap < 9; ++tap) {
                const ulonglong2* wp = (const ulonglong2*)&ws[ci][tap][0];
                ulonglong2 w01 = wp[0], w23 = wp[1], w45 = wp[2], w67 = wp[3];
                u64 vA = pack2(xvA[tap], xvA[tap]);
                u64 vB = pack2(xvB[tap], xvB[tap]);
                fma2(accA[0], vA, w01.x); fma2(accA[1], vA, w01.y);
                fma2(accA[2], vA, w23.x); fma2(accA[3], vA, w23.y);
                fma2(accA[4], vA, w45.x); fma2(accA[5], vA, w45.y);
                fma2(accA[6], vA, w67.x); fma2(accA[7], vA, w67.y);
                fma2(accB[0], vB, w01.x); fma2(accB[1], vB, w01.y);
                fma2(accB[2], vB, w23.x); fma2(accB[3], vB, w23.y);
                fma2(accB[4], vB, w45.x); fma2(accB[5], vB, w45.y);
                fma2(accB[6], vB, w67.x); fma2(accB[7], vB, w67.y);
            }
        }
    }
    size_t obase = ((size_t)b*64 + cog*16) << 14;
    int pA = (r0+ty)*128 + (c0+tx);
    int pB = pA + 16;
#pragma unroll
    for (int p = 0; p < 8; ++p) {
        float bl = __ldg(&b1[cog*16 + 2*p]);
        float bh = __ldg(&b1[cog*16 + 2*p + 1]);
        g_t1[obase + ((size_t)(2*p)   << 14) + pA] = lo32(accA[p]) + bl;
        g_t1[obase + ((size_t)(2*p+1) << 14) + pA] = hi32(accA[p]) + bh;
        g_t1[obase + ((size_t)(2*p)   << 14) + pB] = lo32(accB[p]) + bl;
        g_t1[obase + ((size_t)(2*p+1) << 14) + pB] = hi32(accB[p]) + bh;
    }
}

// ---------------------------------------------------------------------------
// conv2: 1x1, 64->144 (offsets). Block: 64 pixels x 144 oc.
// cp.async fills, double-buffered t1 tile.
// ---------------------------------------------------------------------------
__global__ __launch_bounds__(256) void conv2_kernel(const float* __restrict__ b2,
                                                    float* __restrict__ out_off) {
    __shared__ __align__(16) float w2s[64*144];    // [ci][oc]  36.9KB
    __shared__ __align__(16) float ts[2][16*64];   // [buf][ci*64+pix]  8KB

    int tid = threadIdx.x;
    int pix = tid & 63, ocg = tid >> 6;            // ocg 0..3
    int p0 = blockIdx.x * 64;
    int b  = p0 >> 14;
    int sp = p0 & 16383;

    const float* t1b = g_t1 + (size_t)b*64*16384 + sp;

    for (int i = tid; i < 2304; i += 256) cp16(&w2s[i*4], &g_w2t[i*4]);
    {
        int ci = tid >> 4, q = (tid & 15) * 4;
        cp16(&ts[0][ci*64 + q], t1b + (size_t)ci*16384 + q);
    }
    CP_COMMIT();

    u64 acc[18];
#pragma unroll
    for (int i = 0; i < 18; ++i) acc[i] = 0ull;

    for (int ch = 0; ch < 4; ++ch) {
        CP_WAIT0();
        __syncthreads();
        if (ch < 3) {
            int ci = tid >> 4, q = (tid & 15) * 4;
            cp16(&ts[(ch+1) & 1][ci*64 + q],
                 t1b + (size_t)((ch+1)*16 + ci)*16384 + q);
            CP_COMMIT();
        }
        const float* tsc = ts[ch & 1];
#pragma unroll
        for (int ci = 0; ci < 16; ++ci) {
            float xv = tsc[ci*64 + pix];
            u64 xv2 = pack2(xv, xv);
            const ulonglong2* wp = (const ulonglong2*)&w2s[(ch*16 + ci)*144];
#pragma unroll
            for (int m = 0; m < 9; ++m) {
                ulonglong2 w = wp[ocg + m*4];      // oc = ocg*4 + m*16 + {0..3}
                fma2(acc[2*m],   xv2, w.x);
                fma2(acc[2*m+1], xv2, w.y);
            }
        }
        if (ch < 3) __syncthreads();
    }
    float* ob = out_off + (size_t)b*144*16384 + sp + pix;
#pragma unroll
    for (int m = 0; m < 9; ++m) {
        int oc = ocg*4 + m*16;
        ob[(size_t)(oc  )*16384] = lo32(acc[2*m])   + __ldg(&b2[oc]);
        ob[(size_t)(oc+1)*16384] = hi32(acc[2*m])   + __ldg(&b2[oc+1]);
        ob[(size_t)(oc+2)*16384] = lo32(acc[2*m+1]) + __ldg(&b2[oc+2]);
        ob[(size_t)(oc+3)*16384] = hi32(acc[2*m+1]) + __ldg(&b2[oc+3]);
    }
}

// ---------------------------------------------------------------------------
// deform conv — pipelined: 8 chunks (one offset-group g each, 72 k' values),
// double-buffered v (gather) and weights (cp.async). 55.3KB smem -> 4 CTA/SM.
// Block: 32 pixels of one output row, one batch.
// ---------------------------------------------------------------------------
#define VCHUNK (72*32)     // 2304 floats, 9.2KB
#define WCHUNK (72*64)     // 4608 floats, 18.4KB

__global__ __launch_bounds__(256) void deform_kernel(const float* __restrict__ x,
                                                     const float* __restrict__ off,
                                                     float* __restrict__ yout) {
    extern __shared__ __align__(16) float sm[];
    float* v_s  = sm;                 // 2 x [kk=0..71][pix=0..31]
    float* wd_s = sm + 2*VCHUNK;      // 2 x [kk=0..71][co=0..63]

    int tid = threadIdx.x;
    int b   = blockIdx.z;
    int ho  = blockIdx.y;
    int wo0 = blockIdx.x * 32;

    const float* xbat  = x + (size_t)b*64*16900;
    const float* offb  = off + (size_t)b*144*16384 + (size_t)ho*128 + wo0;

    // Gather one chunk (offset-group g) into vbuf: kk = tap*8 + c.
    auto gather = [&](int g, float* vbuf) {
        for (int t = tid; t < 288; t += 256) {
            int pix = t & 31;
            int tap = t >> 5;
            int i   = tap / 3;
            int j   = tap - i*3;
            int wo  = wo0 + pix;

            const float* op = offb + (size_t)((g*9 + tap)*2)*16384 + pix;
            float dy = op[0];
            float dx = op[16384];
            float py = dy + (float)(ho + i);
            float px = dx + (float)(wo + j);
            float y0f = floorf(py), x0f = floorf(px);
            float ly = py - y0f, lx = px - x0f;
            int y0 = (int)y0f, x0 = (int)x0f;
            int y1 = y0 + 1,  x1 = x0 + 1;

            float my0 = (y0 >= 0 && y0 < 130) ? 1.f : 0.f;
            float my1 = (y1 >= 0 && y1 < 130) ? 1.f : 0.f;
            float mx0 = (x0 >= 0 && x0 < 130) ? 1.f : 0.f;
            float mx1 = (x1 >= 0 && x1 < 130) ? 1.f : 0.f;

            int yc0 = min(max(y0, 0), 129), yc1 = min(max(y1, 0), 129);
            int xc0 = min(max(x0, 0), 129), xc1 = min(max(x1, 0), 129);

            float a00 = (1.f-ly)*(1.f-lx)*my0*mx0;
            float a01 = (1.f-ly)*lx      *my0*mx1;
            float a10 = ly      *(1.f-lx)*my1*mx0;
            float a11 = ly      *lx      *my1*mx1;

            int i00 = yc0*130 + xc0, i01 = yc0*130 + xc1;
            int i10 = yc1*130 + xc0, i11 = yc1*130 + xc1;

            const float* xb = xbat + (size_t)(g*8)*16900;
#pragma unroll
            for (int c = 0; c < 8; ++c) {
                const float* xc = xb + c*16900;
                float v = a00*xc[i00] + a01*xc[i01] + a10*xc[i10] + a11*xc[i11];
                vbuf[(tap*8 + c)*32 + pix] = v;
            }
        }
    };

    // Prologue: prefetch weight chunk 0, gather v chunk 0.
    for (int i = tid; i < WCHUNK/4; i += 256) cp16(wd_s + i*4, g_wd2 + i*4);
    CP_COMMIT();
    gather(0, v_s);
    CP_WAIT0();
    __syncthreads();

    int pix = tid & 31, cg = tid >> 5;    // cg 0..7 -> couts cg*8..cg*8+7
    u64 acc[4];
#pragma unroll
    for (int i = 0; i < 4; ++i) acc[i] = 0ull;

    for (int g = 0; g < 8; ++g) {
        int cur = g & 1, nxt = cur ^ 1;
        if (g < 7) {
            // prefetch next weights + gather next v while GEMM(g) runs below
            float* wn = wd_s + nxt*WCHUNK;
            const float* gsrc = g_wd2 + (g+1)*WCHUNK;
            for (int i = tid; i < WCHUNK/4; i += 256) cp16(wn + i*4, gsrc + i*4);
            CP_COMMIT();
            gather(g+1, v_s + nxt*VCHUNK);
        }

        const float* vb = v_s + cur*VCHUNK + pix;
        const float* wb = wd_s + cur*WCHUNK + cg*8;
#pragma unroll
        for (int kk = 0; kk < 72; ++kk) {
            float xv = vb[kk*32];
            u64 xv2 = pack2(xv, xv);
            const ulonglong2* wp = (const ulonglong2*)(wb + kk*64);
            ulonglong2 wA = wp[0], wB = wp[1];
            fma2(acc[0], xv2, wA.x); fma2(acc[1], xv2, wA.y);
            fma2(acc[2], xv2, wB.x); fma2(acc[3], xv2, wB.y);
        }

        if (g < 7) CP_WAIT0();
        __syncthreads();
    }

    float* yb = yout + ((size_t)b*64 + cg*8)*16384 + (size_t)ho*128 + wo0 + pix;
#pragma unroll
    for (int q = 0; q < 4; ++q) {
        yb[(size_t)(2*q)  *16384] = lo32(acc[q]);
        yb[(size_t)(2*q+1)*16384] = hi32(acc[q]);
    }
}

// ---------------------------------------------------------------------------
extern "C" void kernel_launch(void* const* d_in, const int* in_sizes, int n_in,
                              void* d_out, int out_size) {
    const float* x  = (const float*)d_in[0];
    const float* w1 = (const float*)d_in[1];
    const float* b1 = (const float*)d_in[2];
    const float* w2 = (const float*)d_in[3];
    const float* b2 = (const float*)d_in[4];
    const float* wd = (const float*)d_in[5];

    float* out    = (float*)d_out;
    float* yout   = out;              // y:  [16,64,128,128]
    float* offout = out + YSIZE_;     // off:[16,144,128,128]

    const int DEFORM_SMEM = (2*VCHUNK + 2*WCHUNK) * 4;   // 55296 B
    cudaFuncSetAttribute(deform_kernel,
                         cudaFuncAttributeMaxDynamicSharedMemorySize, DEFORM_SMEM);

    prep_kernel<<<324, 256>>>(w1, w2, wd);
    conv1_kernel<<<dim3(4, 8, 64), 256>>>(x, b1);
    conv2_kernel<<<4096, 256>>>(b2, offout);
    deform_kernel<<<dim3(4, 128, 16), 256, DEFORM_SMEM>>>(x, offout, yout);
}